// round 2
// baseline (speedup 1.0000x reference)
#include <cuda_runtime.h>

#define NUM_SRC 16384
#define NUM_DST 8192
#define N_NBR 50
#define D_FEAT 64
#define K_SEL 10
#define SPITCH 51
#define TOTAL_IDX (NUM_DST * N_NBR)

__device__ int g_deg[NUM_SRC];
__device__ int g_idx[TOTAL_IDX];
__device__ int g_is64;

// Detect whether the neighbor buffer is int64 or int32.
// int64 little-endian values < 2^32 have every odd int32 word == 0.
__global__ void detect_kernel(const int* __restrict__ raw) {
    if (threadIdx.x == 0 && blockIdx.x == 0) {
        int is64 = 1;
        for (int i = 0; i < 512; i++) {
            if (raw[2 * i + 1] != 0) { is64 = 0; break; }
        }
        g_is64 = is64;
    }
}

// Normalize indices to int32 in g_idx (reads 8B/elem only when flag says int64).
__global__ void convert_kernel(const void* __restrict__ raw) {
    int i = blockIdx.x * blockDim.x + threadIdx.x;
    if (i < TOTAL_IDX) {
        int v;
        if (g_is64) v = (int)((const long long*)raw)[i];
        else        v = ((const int*)raw)[i];
        g_idx[i] = v;
    }
}

__global__ void zero_deg_kernel() {
    int i = blockIdx.x * blockDim.x + threadIdx.x;
    if (i < NUM_SRC) g_deg[i] = 0;
}

__global__ void hist_kernel() {
    int i = blockIdx.x * blockDim.x + threadIdx.x;
    if (i < TOTAL_IDX) atomicAdd(&g_deg[g_idx[i]], 1);
}

__global__ __launch_bounds__(128) void dgrec_main_kernel(
    const float* __restrict__ h_src,
    const float* __restrict__ table,
    float* __restrict__ out)
{
    __shared__ int   nbr[N_NBR];
    __shared__ float s[N_NBR * SPITCH];
    __shared__ float cache[N_NBR];
    __shared__ float gains[64];
    __shared__ int   gidx[64];
    __shared__ int   sels[K_SEL];
    __shared__ int   sidx[K_SEL];
    __shared__ float nrmk[K_SEL];

    const int b   = blockIdx.x;
    const int tid = threadIdx.x;

    if (tid < N_NBR) {
        nbr[tid]   = g_idx[b * N_NBR + tid];
        cache[tid] = 0.0f;
    }
    __syncthreads();

    // Gather 50x50 sims submatrix: 2500 random 4B loads (the DRAM-bound part)
    for (int t = tid; t < N_NBR * N_NBR; t += 128) {
        int i = t / N_NBR;
        int j = t - i * N_NBR;
        s[i * SPITCH + j] = __ldg(&table[(size_t)nbr[i] * NUM_SRC + (size_t)nbr[j]]);
    }
    __syncthreads();

    // Greedy max-coverage, K_SEL steps
    for (int k = 0; k < K_SEL; k++) {
        float g = -1.0f;
        if (tid < N_NBR) {
            g = 0.0f;
            const float* srow = &s[tid * SPITCH];
            #pragma unroll
            for (int j = 0; j < N_NBR; j++)
                g += fmaxf(srow[j] - cache[j], 0.0f);
        }
        if (tid < 64) { gains[tid] = g; gidx[tid] = tid; }
        __syncthreads();

        // argmax with first-occurrence tie-break (matches jnp.argmax)
        #pragma unroll
        for (int off = 32; off > 0; off >>= 1) {
            if (tid < off) {
                float gr = gains[tid + off], gl = gains[tid];
                int   ir = gidx[tid + off],  il = gidx[tid];
                if (gr > gl || (gr == gl && ir < il)) {
                    gains[tid] = gr; gidx[tid] = ir;
                }
            }
            __syncthreads();
        }

        int sel = gidx[0];
        if (tid == 0) sels[k] = sel;
        if (tid < N_NBR)
            cache[tid] = fmaxf(cache[tid], s[sel * SPITCH + tid]);
        __syncthreads();
    }

    if (tid < K_SEL) {
        int idx = nbr[sels[tid]];
        sidx[tid] = idx;
        int d = g_deg[idx];
        if (d < 1) d = 1;
        nrmk[tid] = rsqrtf((float)d);
    }
    __syncthreads();

    if (tid < D_FEAT) {
        float acc = 0.0f;
        #pragma unroll
        for (int k = 0; k < K_SEL; k++)
            acc += h_src[(size_t)sidx[k] * D_FEAT + tid] * nrmk[k];
        out[(size_t)b * D_FEAT + tid] = acc * 0.1414213562373095f; // 50^-0.5
    }
}

extern "C" void kernel_launch(void* const* d_in, const int* in_sizes, int n_in,
                              void* d_out, int out_size) {
    // Map inputs by element count (robust to ordering):
    //   h_src: 1,048,576   table: 268,435,456   neighbor_idx: 409,600
    const float* h_src = nullptr;
    const float* table = nullptr;
    const void*  nbrs  = nullptr;
    for (int i = 0; i < n_in; i++) {
        long long sz = in_sizes[i];
        if (sz == (long long)NUM_SRC * NUM_SRC)      table = (const float*)d_in[i];
        else if (sz == (long long)NUM_SRC * D_FEAT)  h_src = (const float*)d_in[i];
        else if (sz == (long long)TOTAL_IDX)         nbrs  = d_in[i];
    }
    float* out = (float*)d_out;

    detect_kernel<<<1, 32>>>((const int*)nbrs);
    convert_kernel<<<(TOTAL_IDX + 255) / 256, 256>>>(nbrs);
    zero_deg_kernel<<<(NUM_SRC + 255) / 256, 256>>>();
    hist_kernel<<<(TOTAL_IDX + 255) / 256, 256>>>();
    dgrec_main_kernel<<<NUM_DST, 128>>>(h_src, table, out);
}

// round 3
// speedup vs baseline: 1.0470x; 1.0470x over previous
#include <cuda_runtime.h>

#define NUM_SRC 16384
#define NUM_DST 8192
#define N_NBR 50
#define D_FEAT 64
#define K_SEL 10
#define SPITCH 51
#define TOTAL_IDX (NUM_DST * N_NBR)
#define NSLOT 20   // ceil(2500/128)

__device__ int g_deg[NUM_SRC];
__device__ int g_idx[TOTAL_IDX];
__device__ int g_is64;

// Kernel A: zero degree array + parallel int64/int32 detection (warp ballot).
__global__ void prep_zero_detect(const int* __restrict__ raw) {
    int i = blockIdx.x * blockDim.x + threadIdx.x;
    if (i < NUM_SRC) g_deg[i] = 0;
    if (blockIdx.x == 0 && threadIdx.x < 32) {
        int bad = 0;
        #pragma unroll
        for (int u = 0; u < 16; u++)
            bad |= (raw[2 * (threadIdx.x * 16 + u) + 1] != 0);
        unsigned m = __ballot_sync(0xffffffffu, bad);
        if (threadIdx.x == 0) g_is64 = (m == 0u);
    }
}

// Kernel B: normalize indices to int32 + degree histogram.
__global__ void prep_convert_hist(const void* __restrict__ raw) {
    int i = blockIdx.x * blockDim.x + threadIdx.x;
    if (i < TOTAL_IDX) {
        int v;
        if (g_is64) v = (int)((const long long*)raw)[i];
        else        v = ((const int*)raw)[i];
        g_idx[i] = v;
        atomicAdd(&g_deg[v], 1);
    }
}

__global__ __launch_bounds__(128) void dgrec_main_kernel(
    const float* __restrict__ h_src,
    const float* __restrict__ table,
    float* __restrict__ out)
{
    __shared__ int   nbr[N_NBR];
    __shared__ float s[N_NBR * SPITCH];
    __shared__ float cache[N_NBR + 14];   // padded so lane+32 reads (<64) stay in-bounds
    __shared__ int   sels[K_SEL];
    __shared__ int   sidx[K_SEL];
    __shared__ float nrmk[K_SEL];

    const int b   = blockIdx.x;
    const int tid = threadIdx.x;

    if (tid < N_NBR) nbr[tid] = g_idx[b * N_NBR + tid];
    if (tid < N_NBR + 14) cache[tid] = 0.0f;
    __syncthreads();

    // ---- Gather 50x50 sims tile with explicit MLP=20 batching ----
    int off[NSLOT];
    #pragma unroll
    for (int u = 0; u < NSLOT; u++) {
        int t = tid + u * 128;
        if (t < N_NBR * N_NBR) {
            int i = t / N_NBR;
            int j = t - i * N_NBR;
            off[u] = nbr[i] * NUM_SRC + nbr[j];
        } else off[u] = 0;
    }
    float v[NSLOT];
    #pragma unroll
    for (int u = 0; u < NSLOT; u++)
        v[u] = __ldg(&table[off[u]]);
    #pragma unroll
    for (int u = 0; u < NSLOT; u++) {
        int t = tid + u * 128;
        if (t < N_NBR * N_NBR) {
            int i = t / N_NBR;
            int j = t - i * N_NBR;
            s[i * SPITCH + j] = v[u];
        }
    }
    __syncthreads();

    // ---- Greedy max-coverage: single warp, shuffle argmax, no block barriers ----
    if (tid < 32) {
        const int lane  = tid;
        const int row0  = lane;             // always valid (<50)
        const int row1  = lane + 32;        // valid only if lane<18
        const bool has1 = (row1 < N_NBR);
        const float* s0 = &s[row0 * SPITCH];
        const float* s1 = &s[(has1 ? row1 : row0) * SPITCH];

        for (int k = 0; k < K_SEL; k++) {
            float g0 = 0.0f, g1 = 0.0f;
            #pragma unroll
            for (int j = 0; j < N_NBR; j++) {
                float c = cache[j];
                g0 += fmaxf(s0[j] - c, 0.0f);
                g1 += fmaxf(s1[j] - c, 0.0f);
            }
            // local pair: row0 < row1, tie -> row0 (first occurrence)
            float g; int idx;
            if (has1 && g1 > g0) { g = g1; idx = row1; }
            else                 { g = g0; idx = row0; }
            // warp argmax, tie -> smaller index
            #pragma unroll
            for (int o = 16; o > 0; o >>= 1) {
                float og = __shfl_down_sync(0xffffffffu, g, o);
                int   oi = __shfl_down_sync(0xffffffffu, idx, o);
                if (og > g || (og == g && oi < idx)) { g = og; idx = oi; }
            }
            int sel = __shfl_sync(0xffffffffu, idx, 0);
            if (lane == 0) sels[k] = sel;
            // cache = max(cache, s[sel])
            const float* srow = &s[sel * SPITCH];
            cache[lane] = fmaxf(cache[lane], srow[lane]);
            if (has1) cache[row1] = fmaxf(cache[row1], srow[row1]);
            __syncwarp();
        }

        if (lane < K_SEL) {
            int idx2 = nbr[sels[lane]];
            sidx[lane] = idx2;
            int d = g_deg[idx2];
            if (d < 1) d = 1;
            nrmk[lane] = rsqrtf((float)d);
        }
    }
    __syncthreads();

    // ---- Output accumulation ----
    if (tid < D_FEAT) {
        float acc = 0.0f;
        #pragma unroll
        for (int k = 0; k < K_SEL; k++)
            acc += h_src[(size_t)sidx[k] * D_FEAT + tid] * nrmk[k];
        out[(size_t)b * D_FEAT + tid] = acc * 0.1414213562373095f; // 50^-0.5
    }
}

extern "C" void kernel_launch(void* const* d_in, const int* in_sizes, int n_in,
                              void* d_out, int out_size) {
    // Map inputs by element count (robust to ordering)
    const float* h_src = nullptr;
    const float* table = nullptr;
    const void*  nbrs  = nullptr;
    for (int i = 0; i < n_in; i++) {
        long long sz = in_sizes[i];
        if (sz == (long long)NUM_SRC * NUM_SRC)      table = (const float*)d_in[i];
        else if (sz == (long long)NUM_SRC * D_FEAT)  h_src = (const float*)d_in[i];
        else if (sz == (long long)TOTAL_IDX)         nbrs  = d_in[i];
    }
    float* out = (float*)d_out;

    prep_zero_detect<<<(NUM_SRC + 255) / 256, 256>>>((const int*)nbrs);
    prep_convert_hist<<<(TOTAL_IDX + 255) / 256, 256>>>(nbrs);
    dgrec_main_kernel<<<NUM_DST, 128>>>(h_src, table, out);
}

// round 4
// speedup vs baseline: 1.1414x; 1.0901x over previous
#include <cuda_runtime.h>

#define NUM_SRC 16384
#define NUM_DST 8192
#define N_NBR 50
#define D_FEAT 64
#define K_SEL 10
#define SPITCH 51
#define TOTAL_IDX (NUM_DST * N_NBR)

__device__ int   g_deg[NUM_SRC];
__device__ int   g_idx[TOTAL_IDX];
__device__ int   g_off[NUM_SRC + 1];
__device__ int   g_cursor[NUM_SRC];
__device__ int   g_uses[TOTAL_IDX];
__device__ float g_tile[(size_t)NUM_DST * N_NBR * N_NBR];   // 82 MB scratch
__device__ int   g_is64;

// K1: zero degree array + int64/int32 detection (warp ballot over first 1024 words)
__global__ void prep_zero_detect(const int* __restrict__ raw) {
    int i = blockIdx.x * blockDim.x + threadIdx.x;
    if (i < NUM_SRC) g_deg[i] = 0;
    if (blockIdx.x == 0 && threadIdx.x < 32) {
        int bad = 0;
        #pragma unroll
        for (int u = 0; u < 16; u++)
            bad |= (raw[2 * (threadIdx.x * 16 + u) + 1] != 0);
        unsigned m = __ballot_sync(0xffffffffu, bad);
        if (threadIdx.x == 0) g_is64 = (m == 0u);
    }
}

// K2: normalize indices to int32 + degree histogram
__global__ void prep_convert_hist(const void* __restrict__ raw) {
    int i = blockIdx.x * blockDim.x + threadIdx.x;
    if (i < TOTAL_IDX) {
        int v;
        if (g_is64) v = (int)((const long long*)raw)[i];
        else        v = ((const int*)raw)[i];
        g_idx[i] = v;
        atomicAdd(&g_deg[v], 1);
    }
}

// K3: exclusive scan of g_deg -> g_off, zero cursors. One block, 512 threads x 32 elems.
__global__ __launch_bounds__(512) void scan_kernel() {
    __shared__ int part[512];
    const int tid  = threadIdx.x;
    const int base = tid * 32;
    int s = 0;
    #pragma unroll
    for (int u = 0; u < 32; u++) s += g_deg[base + u];
    part[tid] = s;
    __syncthreads();
    for (int o = 1; o < 512; o <<= 1) {
        int v = (tid >= o) ? part[tid - o] : 0;
        __syncthreads();
        part[tid] += v;
        __syncthreads();
    }
    int run = part[tid] - s;   // exclusive prefix of this chunk
    #pragma unroll
    for (int u = 0; u < 32; u++) {
        g_off[base + u]    = run;
        g_cursor[base + u] = 0;
        run += g_deg[base + u];
    }
    if (tid == 511) g_off[NUM_SRC] = run;
}

// K4: build CSR uses list: for each flat idx position t, record t under its row.
__global__ void fill_uses() {
    int t = blockIdx.x * blockDim.x + threadIdx.x;
    if (t < TOTAL_IDX) {
        int r   = g_idx[t];
        int pos = atomicAdd(&g_cursor[r], 1);
        g_uses[g_off[r] + pos] = t;
    }
}

// K5: stream the table one row per CTA (coalesced), gather columns from smem,
//     write contiguous 200B tile rows. This converts 655MB of random sectors
//     into 1GB of streaming reads + 82MB of streaming writes.
__global__ __launch_bounds__(512) void row_gather(const float* __restrict__ table) {
    extern __shared__ float srow[];   // 16384 floats = 64KB
    const int r  = blockIdx.x;
    const int n0 = g_off[r];
    const int n1 = g_off[r + 1];
    if (n0 == n1) return;

    // Coalesced row load: 4096 float4 over 512 threads = 8 each
    const float4* src = (const float4*)(table + (size_t)r * NUM_SRC);
    float4* dst = (float4*)srow;
    #pragma unroll
    for (int u = 0; u < NUM_SRC / 4 / 512; u++)
        dst[threadIdx.x + u * 512] = src[threadIdx.x + u * 512];
    __syncthreads();

    // One warp per use; lanes gather 50 columns from smem, write contiguous
    const int wid  = threadIdx.x >> 5;
    const int lane = threadIdx.x & 31;
    for (int u = n0 + wid; u < n1; u += 16) {
        int t    = g_uses[u];            // t = b*50 + i
        int base = t - (t % N_NBR);      // b*50 : start of block b's column list
        float* out = &g_tile[(size_t)t * N_NBR];
        if (lane < N_NBR) {
            out[lane] = srow[g_idx[base + lane]];
            int j = lane + 32;
            if (j < N_NBR) out[j] = srow[g_idx[base + j]];
        }
    }
}

// K6: greedy max-coverage + output. Tile reads now fully coalesced.
__global__ __launch_bounds__(128) void dgrec_greedy_kernel(
    const float* __restrict__ h_src,
    float* __restrict__ out)
{
    __shared__ float s[N_NBR * SPITCH];
    __shared__ float cache[N_NBR + 14];
    __shared__ int   sels[K_SEL];
    __shared__ int   sidx[K_SEL];
    __shared__ float nrmk[K_SEL];

    const int b   = blockIdx.x;
    const int tid = threadIdx.x;

    // Coalesced tile load from scratch, re-pitch to 51 in smem
    const float* tsrc = &g_tile[(size_t)b * N_NBR * N_NBR];
    for (int t = tid; t < N_NBR * N_NBR; t += 128) {
        int i = t / N_NBR;
        s[i * SPITCH + (t - i * N_NBR)] = tsrc[t];
    }
    if (tid < N_NBR + 14) cache[tid] = 0.0f;
    __syncthreads();

    if (tid < 32) {
        const int lane  = tid;
        const int row1  = lane + 32;
        const bool has1 = (row1 < N_NBR);
        const float* s0 = &s[lane * SPITCH];
        const float* s1 = &s[(has1 ? row1 : lane) * SPITCH];

        for (int k = 0; k < K_SEL; k++) {
            float g0 = 0.0f, g1 = 0.0f;
            #pragma unroll
            for (int j = 0; j < N_NBR; j++) {
                float c = cache[j];
                g0 += fmaxf(s0[j] - c, 0.0f);
                g1 += fmaxf(s1[j] - c, 0.0f);
            }
            float g; int idx;
            if (has1 && g1 > g0) { g = g1; idx = row1; }
            else                 { g = g0; idx = lane; }
            #pragma unroll
            for (int o = 16; o > 0; o >>= 1) {
                float og = __shfl_down_sync(0xffffffffu, g, o);
                int   oi = __shfl_down_sync(0xffffffffu, idx, o);
                if (og > g || (og == g && oi < idx)) { g = og; idx = oi; }
            }
            int sel = __shfl_sync(0xffffffffu, idx, 0);
            if (lane == 0) sels[k] = sel;
            const float* srow = &s[sel * SPITCH];
            cache[lane] = fmaxf(cache[lane], srow[lane]);
            if (has1) cache[row1] = fmaxf(cache[row1], srow[row1]);
            __syncwarp();
        }

        if (lane < K_SEL) {
            int t = sels[lane];
            int idx2 = g_idx[b * N_NBR + t];
            sidx[lane] = idx2;
            int d = g_deg[idx2];
            if (d < 1) d = 1;
            nrmk[lane] = rsqrtf((float)d);
        }
    }
    __syncthreads();

    if (tid < D_FEAT) {
        float acc = 0.0f;
        #pragma unroll
        for (int k = 0; k < K_SEL; k++)
            acc += h_src[(size_t)sidx[k] * D_FEAT + tid] * nrmk[k];
        out[(size_t)b * D_FEAT + tid] = acc * 0.1414213562373095f; // 50^-0.5
    }
}

extern "C" void kernel_launch(void* const* d_in, const int* in_sizes, int n_in,
                              void* d_out, int out_size) {
    const float* h_src = nullptr;
    const float* table = nullptr;
    const void*  nbrs  = nullptr;
    for (int i = 0; i < n_in; i++) {
        long long sz = in_sizes[i];
        if (sz == (long long)NUM_SRC * NUM_SRC)      table = (const float*)d_in[i];
        else if (sz == (long long)NUM_SRC * D_FEAT)  h_src = (const float*)d_in[i];
        else if (sz == (long long)TOTAL_IDX)         nbrs  = d_in[i];
    }
    float* out = (float*)d_out;

    cudaFuncSetAttribute(row_gather, cudaFuncAttributeMaxDynamicSharedMemorySize,
                         NUM_SRC * (int)sizeof(float));

    prep_zero_detect<<<(NUM_SRC + 255) / 256, 256>>>((const int*)nbrs);
    prep_convert_hist<<<(TOTAL_IDX + 255) / 256, 256>>>(nbrs);
    scan_kernel<<<1, 512>>>();
    fill_uses<<<(TOTAL_IDX + 255) / 256, 256>>>();
    row_gather<<<NUM_SRC, 512, NUM_SRC * sizeof(float)>>>(table);
    dgrec_greedy_kernel<<<NUM_DST, 128>>>(h_src, out);
}